// round 4
// baseline (speedup 1.0000x reference)
#include <cuda_runtime.h>
#include <cuda_fp16.h>
#include <cstdint>

#define M_TOTAL 12608   // 64*197
#define K_DIM   768
#define R_DIM   192
#define BM      128
#define BN      64
#define BK      64      // fp16 elems per chunk = 128 bytes/row
#define NCHUNK  12      // 768/64
#define A_BYTES (BM * 128)           // 16384
#define B_BYTES (BN * 128)           // 8192
#define STAGE   (A_BYTES + B_BYTES)  // 24576
#define NSTAGE  4
#define SMEM_DYN (NSTAGE * STAGE + 1024)

#define NTILES  891                  // 9 * 99
#define NCTA    296                  // 148 SMs * 2

#define SWZ(o) ((o) ^ (((o) >> 3) & 0x70))

// fp16 scratch (allocation-free __device__ globals)
__device__ __half g_Xh[(size_t)M_TOTAL * K_DIM];     // [M,K] row-major
__device__ __half g_Wh[(size_t)3 * R_DIM * K_DIM];   // [3][N=192][K=768] K-major

// ---------------- PTX helpers (sm_80-portable only) ----------------
__device__ __forceinline__ uint32_t smem_u32(const void* p) {
    uint32_t a;
    asm("{ .reg .u64 t; cvta.to.shared.u64 t, %1; cvt.u32.u64 %0, t; }" : "=r"(a) : "l"(p));
    return a;
}
__device__ __forceinline__ void cp16(uint32_t dst, const void* src) {
    asm volatile("cp.async.cg.shared.global [%0], [%1], 16;" :: "r"(dst), "l"(src) : "memory");
}
__device__ __forceinline__ void cp16z(uint32_t dst, const void* src, int srcbytes) {
    asm volatile("cp.async.cg.shared.global [%0], [%1], 16, %2;"
                 :: "r"(dst), "l"(src), "r"(srcbytes) : "memory");
}
#define CP_COMMIT() asm volatile("cp.async.commit_group;" ::: "memory")
#define CP_WAIT0()  asm volatile("cp.async.wait_group 0;" ::: "memory")
#define CP_WAIT1()  asm volatile("cp.async.wait_group 1;" ::: "memory")
#define CP_WAIT2()  asm volatile("cp.async.wait_group 2;" ::: "memory")

__device__ __forceinline__ void ldsm4(uint32_t* r, uint32_t addr) {
    asm volatile("ldmatrix.sync.aligned.m8n8.x4.shared.b16 {%0,%1,%2,%3}, [%4];"
                 : "=r"(r[0]), "=r"(r[1]), "=r"(r[2]), "=r"(r[3]) : "r"(addr));
}
__device__ __forceinline__ void mma16816(float* c, const uint32_t* a, const uint32_t* b) {
    asm volatile(
        "mma.sync.aligned.m16n8k16.row.col.f32.f16.f16.f32 "
        "{%0,%1,%2,%3}, {%4,%5,%6,%7}, {%8,%9}, {%0,%1,%2,%3};"
        : "+f"(c[0]), "+f"(c[1]), "+f"(c[2]), "+f"(c[3])
        : "r"(a[0]), "r"(a[1]), "r"(a[2]), "r"(a[3]), "r"(b[0]), "r"(b[1]));
}
__device__ __forceinline__ float gelu_exact(float x) {
    return 0.5f * x * (1.0f + erff(x * 0.70710678118654752f));
}

// ---------------- convert prepasses ----------------
__global__ __launch_bounds__(256, 4)
void cvt_x_kernel(const float4* __restrict__ X, uint2* __restrict__ out, int n4) {
    const int t = blockIdx.x * blockDim.x + threadIdx.x;
    const int stride = gridDim.x * blockDim.x;
    float4 v[4];
    #pragma unroll
    for (int u = 0; u < 4; ++u) {
        int i = t + u * stride;
        if (i < n4) v[u] = X[i];
    }
    #pragma unroll
    for (int u = 0; u < 4; ++u) {
        int i = t + u * stride;
        if (i < n4) {
            __half2 h0 = __floats2half2_rn(v[u].x, v[u].y);
            __half2 h1 = __floats2half2_rn(v[u].z, v[u].w);
            uint2 o;
            o.x = *reinterpret_cast<uint32_t*>(&h0);
            o.y = *reinterpret_cast<uint32_t*>(&h1);
            out[i] = o;
        }
    }
}
__global__ void cvt_w_kernel(const float* __restrict__ Wq, const float* __restrict__ Wk,
                             const float* __restrict__ Wv) {
    int idx = blockIdx.x * blockDim.x + threadIdx.x;
    const int per = R_DIM * K_DIM;
    if (idx < 3 * per) {
        int w = idx / per;
        int rem = idx - w * per;
        int n = rem / K_DIM;
        int k = rem - n * K_DIM;
        const float* W = (w == 0) ? Wq : (w == 1) ? Wk : Wv;
        g_Wh[idx] = __float2half_rn(W[k * R_DIM + n]);   // transpose -> K-major
    }
}

// ---------------- chunk loader (cp.async, swizzled 128B rows) ----------------
// Global chunk index g -> tile T = cta + (g/12)*NCTA, chunk c = g%12.
__device__ __forceinline__ void load_chunk(int g, uint32_t st_sm, int cta, int tid) {
    const int i = g / NCHUNK;
    const int c = g - i * NCHUNK;
    const int T = cta + i * NCTA;
    const int nb = T % 9;
    const int bm = (T / 9) * BM;
    const int wsel   = nb / 3;
    const int colofs = (nb % 3) * BN;
    const __half* Asrc = g_Xh + (size_t)bm * K_DIM + c * BK;
    const __half* Bsrc = g_Wh + ((size_t)wsel * R_DIM + colofs) * K_DIM + c * BK;

    // A tile: 128 rows x 8 16B-chunks = 1024 -> 4 per thread
    #pragma unroll
    for (int u = 0; u < 4; ++u) {
        int idx = tid + u * 256;
        int row = idx >> 3;
        int j   = idx & 7;
        int grow = bm + row;
        size_t roff = (grow < M_TOTAL) ? (size_t)row * K_DIM : 0;
        cp16z(st_sm + SWZ(row * 128 + j * 16), Asrc + roff + j * 8,
              (grow < M_TOTAL) ? 16 : 0);
    }
    // B tile: 64 rows x 8 = 512 -> 2 per thread
    #pragma unroll
    for (int u = 0; u < 2; ++u) {
        int idx = tid + u * 256;
        int row = idx >> 3;
        int j   = idx & 7;
        cp16(st_sm + A_BYTES + SWZ(row * 128 + j * 16),
             Bsrc + (size_t)row * K_DIM + j * 8);
    }
}

// ---------------- persistent GEMM (mma.sync HMMA, 4-stage pipeline) ----------------
__global__ __launch_bounds__(256, 2)
void qkv_mma_kernel(float* __restrict__ Out) {
    extern __shared__ char dynsm[];
    const int tid  = threadIdx.x;
    const int wid  = tid >> 5;
    const int lane = tid & 31;
    const int cta  = blockIdx.x;

    const int ntile = (cta < (NTILES % NCTA)) ? (NTILES / NCTA + 1) : (NTILES / NCTA);
    const int total = ntile * NCHUNK;

    const int warp_m = (wid & 3) * 32;        // 0,32,64,96
    const int warp_n = (wid >> 2) * 32;       // 0,32

    uint32_t base = (smem_u32(dynsm) + 1023u) & ~1023u;

    // per-lane ldmatrix offsets
    const int a_row_off = lane & 15;
    const int a_k_off   = (lane >> 4) * 16;
    const int b_n_off   = (lane & 7) | ((lane & 16) >> 1);
    const int b_k_off   = (lane & 8) ? 16 : 0;

    float acc[2][4][4];
    #pragma unroll
    for (int i = 0; i < 2; ++i)
        #pragma unroll
        for (int j = 0; j < 4; ++j)
            #pragma unroll
            for (int q = 0; q < 4; ++q) acc[i][j][q] = 0.0f;

    // prologue: stages 0..2 in flight
    #pragma unroll
    for (int g = 0; g < NSTAGE - 1; ++g) {
        load_chunk(g, base + (g % NSTAGE) * STAGE, cta, tid);
        CP_COMMIT();
    }

    for (int j = 0; j < total; ++j) {
        // group j must be resident
        if (j + 2 < total)      { CP_WAIT2(); }
        else if (j + 1 < total) { CP_WAIT1(); }
        else                    { CP_WAIT0(); }
        __syncthreads();

        // issue lookahead loads (stage (j+3)%4; readers this iter use j%4)
        if (j + NSTAGE - 1 < total) {
            load_chunk(j + NSTAGE - 1, base + ((j + NSTAGE - 1) % NSTAGE) * STAGE, cta, tid);
            CP_COMMIT();
        }

        const uint32_t a_sm = base + (j % NSTAGE) * STAGE;
        const uint32_t b_sm = a_sm + A_BYTES;

        #pragma unroll
        for (int ks = 0; ks < 4; ++ks) {
            uint32_t afrag[2][4], bfrag[2][4];
            #pragma unroll
            for (int mf = 0; mf < 2; ++mf)
                ldsm4(afrag[mf],
                      a_sm + SWZ((warp_m + mf * 16 + a_row_off) * 128 + ks * 32 + a_k_off));
            #pragma unroll
            for (int nf2 = 0; nf2 < 2; ++nf2)
                ldsm4(bfrag[nf2],
                      b_sm + SWZ((warp_n + nf2 * 16 + b_n_off) * 128 + ks * 32 + b_k_off));
            #pragma unroll
            for (int mf = 0; mf < 2; ++mf)
                #pragma unroll
                for (int nf = 0; nf < 4; ++nf)
                    mma16816(acc[mf][nf], afrag[mf], &bfrag[nf >> 1][(nf & 1) * 2]);
        }

        // tile boundary: epilogue + reset accumulators
        if ((j % NCHUNK) == NCHUNK - 1) {
            const int T = cta + (j / NCHUNK) * NCTA;
            const int nb = T % 9;
            const int bm = (T / 9) * BM;
            const int wsel   = nb / 3;
            const int colofs = (nb % 3) * BN;
            float* __restrict__ outbase =
                Out + (size_t)wsel * (size_t)M_TOTAL * R_DIM + colofs;

            const int rbase = bm + warp_m + (lane >> 2);
            const int cbase = warp_n + (lane & 3) * 2;
            #pragma unroll
            for (int mf = 0; mf < 2; ++mf) {
                #pragma unroll
                for (int half = 0; half < 2; ++half) {
                    int row = rbase + mf * 16 + half * 8;
                    if (row < M_TOTAL) {
                        float* op = outbase + (size_t)row * R_DIM + cbase;
                        #pragma unroll
                        for (int nf = 0; nf < 4; ++nf) {
                            float2 o;
                            o.x = gelu_exact(acc[mf][nf][half * 2 + 0]);
                            o.y = gelu_exact(acc[mf][nf][half * 2 + 1]);
                            *reinterpret_cast<float2*>(op + nf * 8) = o;
                        }
                    }
                }
            }
            #pragma unroll
            for (int i = 0; i < 2; ++i)
                #pragma unroll
                for (int jj = 0; jj < 4; ++jj)
                    #pragma unroll
                    for (int q = 0; q < 4; ++q) acc[i][jj][q] = 0.0f;
        }
    }
}

extern "C" void kernel_launch(void* const* d_in, const int* in_sizes, int n_in,
                              void* d_out, int out_size) {
    const float* X  = (const float*)d_in[0];  // [64,197,768]
    const float* Wq = (const float*)d_in[1];  // [768,192]
    const float* Wk = (const float*)d_in[2];
    const float* Wv = (const float*)d_in[3];
    float* Out = (float*)d_out;

    cudaFuncSetAttribute(qkv_mma_kernel, cudaFuncAttributeMaxDynamicSharedMemorySize, SMEM_DYN);

    __half* xh_ptr = nullptr;
    cudaGetSymbolAddress((void**)&xh_ptr, g_Xh);

    const int n4 = (M_TOTAL * K_DIM) / 4;                 // 2420736
    cvt_x_kernel<<<(n4 / 4 + 255) / 256, 256>>>((const float4*)X, (uint2*)xh_ptr, n4);
    cvt_w_kernel<<<(3 * R_DIM * K_DIM + 255) / 256, 256>>>(Wq, Wk, Wv);

    qkv_mma_kernel<<<NCTA, 256, SMEM_DYN>>>(Out);
}

// round 5
// speedup vs baseline: 1.0413x; 1.0413x over previous
#include <cuda_runtime.h>
#include <cuda_fp16.h>
#include <cstdint>

#define M_TOTAL 12608   // 64*197
#define K_DIM   768
#define R_DIM   192
#define BM      128
#define BN      64
#define BK      64      // K elems per chunk (fp16 row = 128B)
#define NCHUNK  12
#define A16_BYTES (BM * 128)     // 16384
#define B_BYTES   (BN * 128)     // 8192
#define NB_STAGE  4
#define SMEM_DYN (2 * A16_BYTES + NB_STAGE * B_BYTES + 1024)

#define SWZ(o) ((o) ^ (((o) >> 3) & 0x70))

// fp16 weights, K-major (allocation-free __device__ global)
__device__ __half g_Wh[(size_t)3 * R_DIM * K_DIM];   // [3][N=192][K=768]

// ---------------- PTX helpers ----------------
__device__ __forceinline__ uint32_t smem_u32(const void* p) {
    uint32_t a;
    asm("{ .reg .u64 t; cvta.to.shared.u64 t, %1; cvt.u32.u64 %0, t; }" : "=r"(a) : "l"(p));
    return a;
}
__device__ __forceinline__ void cp16(uint32_t dst, const void* src) {
    asm volatile("cp.async.cg.shared.global [%0], [%1], 16;" :: "r"(dst), "l"(src) : "memory");
}
#define CP_COMMIT() asm volatile("cp.async.commit_group;" ::: "memory")
#define CP_WAIT0()  asm volatile("cp.async.wait_group 0;" ::: "memory")
#define CP_WAIT1()  asm volatile("cp.async.wait_group 1;" ::: "memory")

__device__ __forceinline__ void ldsm4(uint32_t* r, uint32_t addr) {
    asm volatile("ldmatrix.sync.aligned.m8n8.x4.shared.b16 {%0,%1,%2,%3}, [%4];"
                 : "=r"(r[0]), "=r"(r[1]), "=r"(r[2]), "=r"(r[3]) : "r"(addr));
}
__device__ __forceinline__ void mma16816(float* c, const uint32_t* a, const uint32_t* b) {
    asm volatile(
        "mma.sync.aligned.m16n8k16.row.col.f32.f16.f16.f32 "
        "{%0,%1,%2,%3}, {%4,%5,%6,%7}, {%8,%9}, {%0,%1,%2,%3};"
        : "+f"(c[0]), "+f"(c[1]), "+f"(c[2]), "+f"(c[3])
        : "r"(a[0]), "r"(a[1]), "r"(a[2]), "r"(a[3]), "r"(b[0]), "r"(b[1]));
}
__device__ __forceinline__ void sts64(uint32_t addr, uint32_t u0, uint32_t u1) {
    asm volatile("st.shared.v2.b32 [%0], {%1, %2};" :: "r"(addr), "r"(u0), "r"(u1) : "memory");
}
__device__ __forceinline__ float gelu_exact(float x) {
    return 0.5f * x * (1.0f + erff(x * 0.70710678118654752f));
}

// ---------------- weight convert prepass ----------------
__global__ void cvt_w_kernel(const float* __restrict__ Wq, const float* __restrict__ Wk,
                             const float* __restrict__ Wv) {
    int idx = blockIdx.x * blockDim.x + threadIdx.x;
    const int per = R_DIM * K_DIM;
    if (idx < 3 * per) {
        int w = idx / per;
        int rem = idx - w * per;
        int n = rem / K_DIM;
        int k = rem - n * K_DIM;
        const float* W = (w == 0) ? Wq : (w == 1) ? Wk : Wv;
        g_Wh[idx] = __float2half_rn(W[k * R_DIM + n]);   // transpose -> K-major
    }
}

// ---------------- fused GEMM: fp32 X -> reg cvt -> fp16 smem -> HMMA ----------------
__global__ __launch_bounds__(256, 2)
void qkv_mma_kernel(const float* __restrict__ X, float* __restrict__ Out) {
    extern __shared__ char dynsm[];
    const int tid  = threadIdx.x;
    const int wid  = tid >> 5;
    const int lane = tid & 31;
    const int nb   = blockIdx.x;              // 0..8
    const int bm   = blockIdx.y * BM;

    const int wsel   = nb / 3;
    const int colofs = (nb % 3) * BN;
    float* __restrict__ outbase =
        Out + (size_t)wsel * (size_t)M_TOTAL * R_DIM + colofs;

    const int warp_m = (wid & 3) * 32;        // 0,32,64,96
    const int warp_n = (wid >> 2) * 32;       // 0,32

    uint32_t base = (smem_u32(dynsm) + 1023u) & ~1023u;
    const uint32_t a16 = base;                          // 2 x 16KB
    const uint32_t bsm = base + 2 * A16_BYTES;          // 4 x 8KB ring

    const float*  Asrc = X + (size_t)bm * K_DIM;
    const __half* Bsrc = g_Wh + ((size_t)wsel * R_DIM + colofs) * K_DIM;

    // per-thread A mapping: 8 float4 per chunk; row = row0 + 16i, 16B-col = c16
    const int row0 = tid >> 4;        // 0..15
    const int c16  = tid & 15;        // 0..15

    // per-lane ldmatrix offsets
    const int a_row_off = lane & 15;
    const int a_k_off   = (lane >> 4) * 16;
    const int b_n_off   = (lane & 7) | ((lane & 16) >> 1);
    const int b_k_off   = (lane & 8) ? 16 : 0;

    float4 astage[8];

    float acc[2][4][4];
    #pragma unroll
    for (int i = 0; i < 2; ++i)
        #pragma unroll
        for (int j = 0; j < 4; ++j)
            #pragma unroll
            for (int q = 0; q < 4; ++q) acc[i][j][q] = 0.0f;

    // ---- A path: LDG fp32 -> regs
    auto ldg_a = [&](int c) {
        #pragma unroll
        for (int i = 0; i < 8; ++i) {
            int row  = row0 + i * 16;
            int grow = bm + row;
            if (grow < M_TOTAL)
                astage[i] = *reinterpret_cast<const float4*>(
                    Asrc + (size_t)row * K_DIM + c * BK + c16 * 4);
            else
                astage[i] = make_float4(0.f, 0.f, 0.f, 0.f);
        }
    };
    // regs -> cvt -> swizzled fp16 STS
    auto cvt_sts = [&](uint32_t a_dst) {
        #pragma unroll
        for (int i = 0; i < 8; ++i) {
            int row = row0 + i * 16;
            __half2 h0 = __floats2half2_rn(astage[i].x, astage[i].y);
            __half2 h1 = __floats2half2_rn(astage[i].z, astage[i].w);
            sts64(a_dst + SWZ(row * 128 + c16 * 8),
                  *reinterpret_cast<uint32_t*>(&h0),
                  *reinterpret_cast<uint32_t*>(&h1));
        }
    };
    // ---- B path: cp.async fp16 (512 x 16B -> 2 per thread)
    auto ldb = [&](int c, uint32_t b_dst) {
        #pragma unroll
        for (int u = 0; u < 2; ++u) {
            int idx = tid + u * 256;
            int row = idx >> 3;
            int j   = idx & 7;
            cp16(b_dst + SWZ(row * 128 + j * 16),
                 Bsrc + (size_t)row * K_DIM + c * BK + j * 8);
        }
    };

    // ---- prologue: A0 in regs->smem[0]; B0,B1 in flight
    ldg_a(0);
    ldb(0, bsm);             CP_COMMIT();
    ldb(1, bsm + B_BYTES);   CP_COMMIT();
    cvt_sts(a16);

    for (int j = 0; j < NCHUNK; ++j) {
        if (j + 1 < NCHUNK) { CP_WAIT1(); } else { CP_WAIT0(); }
        __syncthreads();     // A16[j&1] written by all; B[j%4] resident

        if (j + 2 < NCHUNK) {
            ldb(j + 2, bsm + ((j + 2) % NB_STAGE) * B_BYTES);
            CP_COMMIT();
        }
        if (j + 1 < NCHUNK) ldg_a(j + 1);    // LDG latency hidden under MMA loop

        const uint32_t a_sm = a16 + (j & 1) * A16_BYTES;
        const uint32_t b_sm = bsm + (j % NB_STAGE) * B_BYTES;

        #pragma unroll
        for (int ks = 0; ks < 4; ++ks) {
            uint32_t afrag[2][4], bfrag[2][4];
            #pragma unroll
            for (int mf = 0; mf < 2; ++mf)
                ldsm4(afrag[mf],
                      a_sm + SWZ((warp_m + mf * 16 + a_row_off) * 128 + ks * 32 + a_k_off));
            #pragma unroll
            for (int nf2 = 0; nf2 < 2; ++nf2)
                ldsm4(bfrag[nf2],
                      b_sm + SWZ((warp_n + nf2 * 16 + b_n_off) * 128 + ks * 32 + b_k_off));
            #pragma unroll
            for (int mf = 0; mf < 2; ++mf)
                #pragma unroll
                for (int nf = 0; nf < 4; ++nf)
                    mma16816(acc[mf][nf], afrag[mf], &bfrag[nf >> 1][(nf & 1) * 2]);
        }

        if (j + 1 < NCHUNK) cvt_sts(a16 + ((j + 1) & 1) * A16_BYTES);
    }

    // ---- epilogue: GELU + float2 stores
    const int rbase = bm + warp_m + (lane >> 2);
    const int cbase = warp_n + (lane & 3) * 2;
    #pragma unroll
    for (int mf = 0; mf < 2; ++mf) {
        #pragma unroll
        for (int half = 0; half < 2; ++half) {
            int row = rbase + mf * 16 + half * 8;
            if (row < M_TOTAL) {
                float* op = outbase + (size_t)row * R_DIM + cbase;
                #pragma unroll
                for (int nf = 0; nf < 4; ++nf) {
                    float2 o;
                    o.x = gelu_exact(acc[mf][nf][half * 2 + 0]);
                    o.y = gelu_exact(acc[mf][nf][half * 2 + 1]);
                    *reinterpret_cast<float2*>(op + nf * 8) = o;
                }
            }
        }
    }
}

extern "C" void kernel_launch(void* const* d_in, const int* in_sizes, int n_in,
                              void* d_out, int out_size) {
    const float* X  = (const float*)d_in[0];  // [64,197,768]
    const float* Wq = (const float*)d_in[1];  // [768,192]
    const float* Wk = (const float*)d_in[2];
    const float* Wv = (const float*)d_in[3];
    float* Out = (float*)d_out;

    cudaFuncSetAttribute(qkv_mma_kernel, cudaFuncAttributeMaxDynamicSharedMemorySize, SMEM_DYN);

    cvt_w_kernel<<<(3 * R_DIM * K_DIM + 255) / 256, 256>>>(Wq, Wk, Wv);

    dim3 grid(9, (M_TOTAL + BM - 1) / BM);    // 9 x 99 = 891 CTAs
    qkv_mma_kernel<<<grid, 256, SMEM_DYN>>>(X, Out);
}

// round 6
// speedup vs baseline: 1.1415x; 1.0962x over previous
#include <cuda_runtime.h>
#include <cuda_fp16.h>
#include <cstdint>

#define M_TOTAL 12608   // 64*197 (divisible by 64 -> no M guards)
#define K_DIM   768
#define R_DIM   192
#define BM      64
#define BN      192
#define BK      64      // fp16 elems per chunk = 128B row
#define NCHUNK  12
#define A_BYTES (BM * 128)            // 8192
#define B_BYTES (BN * 128)            // 24576
#define STAGE   (A_BYTES + B_BYTES)   // 32768
#define NSTAGE  3
#define SMEM_DYN (NSTAGE * STAGE + 1024)   // ~97KB -> 2 CTA/SM

#define SWZ(o) ((o) ^ (((o) >> 3) & 0x70))

// fp16 scratch (allocation-free __device__ globals)
__device__ __half g_Xh[(size_t)M_TOTAL * K_DIM];     // [M,K] row-major
__device__ __half g_Wh[(size_t)3 * R_DIM * K_DIM];   // [3][N=192][K=768] K-major

// ---------------- PTX helpers ----------------
__device__ __forceinline__ uint32_t smem_u32(const void* p) {
    uint32_t a;
    asm("{ .reg .u64 t; cvta.to.shared.u64 t, %1; cvt.u32.u64 %0, t; }" : "=r"(a) : "l"(p));
    return a;
}
__device__ __forceinline__ void cp16(uint32_t dst, const void* src) {
    asm volatile("cp.async.cg.shared.global [%0], [%1], 16;" :: "r"(dst), "l"(src) : "memory");
}
#define CP_COMMIT() asm volatile("cp.async.commit_group;" ::: "memory")
#define CP_WAIT0()  asm volatile("cp.async.wait_group 0;" ::: "memory")
#define CP_WAIT1()  asm volatile("cp.async.wait_group 1;" ::: "memory")

__device__ __forceinline__ void ldsm4(uint32_t* r, uint32_t addr) {
    asm volatile("ldmatrix.sync.aligned.m8n8.x4.shared.b16 {%0,%1,%2,%3}, [%4];"
                 : "=r"(r[0]), "=r"(r[1]), "=r"(r[2]), "=r"(r[3]) : "r"(addr));
}
__device__ __forceinline__ void mma16816(float* c, const uint32_t* a, const uint32_t* b) {
    asm volatile(
        "mma.sync.aligned.m16n8k16.row.col.f32.f16.f16.f32 "
        "{%0,%1,%2,%3}, {%4,%5,%6,%7}, {%8,%9}, {%0,%1,%2,%3};"
        : "+f"(c[0]), "+f"(c[1]), "+f"(c[2]), "+f"(c[3])
        : "r"(a[0]), "r"(a[1]), "r"(a[2]), "r"(a[3]), "r"(b[0]), "r"(b[1]));
}
__device__ __forceinline__ float gelu_exact(float x) {
    return 0.5f * x * (1.0f + erff(x * 0.70710678118654752f));
}

// ---------------- convert prepasses ----------------
__global__ __launch_bounds__(256, 4)
void cvt_x_kernel(const float4* __restrict__ X, uint2* __restrict__ out, int n4) {
    const int t = blockIdx.x * blockDim.x + threadIdx.x;
    const int stride = gridDim.x * blockDim.x;
    float4 v[4];
    #pragma unroll
    for (int u = 0; u < 4; ++u) {
        int i = t + u * stride;
        if (i < n4) v[u] = X[i];
    }
    #pragma unroll
    for (int u = 0; u < 4; ++u) {
        int i = t + u * stride;
        if (i < n4) {
            __half2 h0 = __floats2half2_rn(v[u].x, v[u].y);
            __half2 h1 = __floats2half2_rn(v[u].z, v[u].w);
            uint2 o;
            o.x = *reinterpret_cast<uint32_t*>(&h0);
            o.y = *reinterpret_cast<uint32_t*>(&h1);
            out[i] = o;
        }
    }
}
__global__ void cvt_w_kernel(const float* __restrict__ Wq, const float* __restrict__ Wk,
                             const float* __restrict__ Wv) {
    int idx = blockIdx.x * blockDim.x + threadIdx.x;
    const int per = R_DIM * K_DIM;
    if (idx < 3 * per) {
        int w = idx / per;
        int rem = idx - w * per;
        int n = rem / K_DIM;
        int k = rem - n * K_DIM;
        const float* W = (w == 0) ? Wq : (w == 1) ? Wk : Wv;
        g_Wh[idx] = __float2half_rn(W[k * R_DIM + n]);   // transpose -> K-major
    }
}

// ---------------- chunk loader (cp.async, swizzled 128B rows) ----------------
__device__ __forceinline__ void load_chunk(int c, uint32_t st, const __half* Asrc,
                                           const __half* Bsrc, int tid) {
    // A: 64 rows x 8 16B-chunks = 512 -> 4 per thread (128 threads)
    #pragma unroll
    for (int u = 0; u < 4; ++u) {
        int idx = tid + u * 128;
        int row = idx >> 3;
        int j   = idx & 7;
        cp16(st + SWZ(row * 128 + j * 16),
             Asrc + (size_t)row * K_DIM + c * BK + j * 8);
    }
    // B: 192 rows x 8 = 1536 -> 12 per thread
    #pragma unroll
    for (int u = 0; u < 12; ++u) {
        int idx = tid + u * 128;
        int row = idx >> 3;
        int j   = idx & 7;
        cp16(st + A_BYTES + SWZ(row * 128 + j * 16),
             Bsrc + (size_t)row * K_DIM + c * BK + j * 8);
    }
}

// ---------------- GEMM: CTA 64x192, 4 warps (1x4), warp tile 64x48 ----------------
__global__ __launch_bounds__(128, 2)
void qkv_mma_kernel(float* __restrict__ Out) {
    extern __shared__ char dynsm[];
    const int tid  = threadIdx.x;
    const int wid  = tid >> 5;                // 0..3
    const int lane = tid & 31;
    const int nb   = blockIdx.x;              // 0..2 -> q/k/v
    const int bm   = blockIdx.y * BM;

    const int warp_n = wid * 48;

    uint32_t base = (smem_u32(dynsm) + 1023u) & ~1023u;

    const __half* Asrc = g_Xh + (size_t)bm * K_DIM;
    const __half* Bsrc = g_Wh + (size_t)nb * R_DIM * K_DIM;

    // per-lane ldmatrix offsets
    const int a_row_off = lane & 15;
    const int a_k_off   = (lane >> 4) * 16;
    const int b_n_off   = (lane & 7) | ((lane & 16) >> 1);
    const int b_k_off   = (lane & 8) ? 16 : 0;

    float acc[4][6][4];
    #pragma unroll
    for (int i = 0; i < 4; ++i)
        #pragma unroll
        for (int j = 0; j < 6; ++j)
            #pragma unroll
            for (int q = 0; q < 4; ++q) acc[i][j][q] = 0.0f;

    // prologue: chunks 0,1 in flight
    load_chunk(0, base, Asrc, Bsrc, tid);             CP_COMMIT();
    load_chunk(1, base + STAGE, Asrc, Bsrc, tid);     CP_COMMIT();

    for (int j = 0; j < NCHUNK; ++j) {
        if (j + 1 < NCHUNK) { CP_WAIT1(); } else { CP_WAIT0(); }
        __syncthreads();

        if (j + 2 < NCHUNK) {
            load_chunk(j + 2, base + ((j + 2) % NSTAGE) * STAGE, Asrc, Bsrc, tid);
            CP_COMMIT();
        }

        const uint32_t a_sm = base + (j % NSTAGE) * STAGE;
        const uint32_t b_sm = a_sm + A_BYTES;

        #pragma unroll
        for (int ks = 0; ks < 4; ++ks) {
            uint32_t afrag[4][4], bfrag[3][4];
            #pragma unroll
            for (int mf = 0; mf < 4; ++mf)
                ldsm4(afrag[mf],
                      a_sm + SWZ((mf * 16 + a_row_off) * 128 + ks * 32 + a_k_off));
            #pragma unroll
            for (int nf2 = 0; nf2 < 3; ++nf2)
                ldsm4(bfrag[nf2],
                      b_sm + SWZ((warp_n + nf2 * 16 + b_n_off) * 128 + ks * 32 + b_k_off));
            #pragma unroll
            for (int mf = 0; mf < 4; ++mf)
                #pragma unroll
                for (int nf = 0; nf < 6; ++nf)
                    mma16816(acc[mf][nf], afrag[mf], &bfrag[nf >> 1][(nf & 1) * 2]);
        }
    }

    // ---- epilogue: GELU + float2 stores (no M guards: 12608 % 64 == 0)
    float* __restrict__ outbase =
        Out + (size_t)nb * (size_t)M_TOTAL * R_DIM + warp_n;
    const int rbase = bm + (lane >> 2);
    const int cbase = (lane & 3) * 2;
    #pragma unroll
    for (int mf = 0; mf < 4; ++mf) {
        #pragma unroll
        for (int half = 0; half < 2; ++half) {
            int row = rbase + mf * 16 + half * 8;
            float* op = outbase + (size_t)row * R_DIM + cbase;
            #pragma unroll
            for (int nf = 0; nf < 6; ++nf) {
                float2 o;
                o.x = gelu_exact(acc[mf][nf][half * 2 + 0]);
                o.y = gelu_exact(acc[mf][nf][half * 2 + 1]);
                *reinterpret_cast<float2*>(op + nf * 8) = o;
            }
        }
    }
}

extern "C" void kernel_launch(void* const* d_in, const int* in_sizes, int n_in,
                              void* d_out, int out_size) {
    const float* X  = (const float*)d_in[0];  // [64,197,768]
    const float* Wq = (const float*)d_in[1];  // [768,192]
    const float* Wk = (const float*)d_in[2];
    const float* Wv = (const float*)d_in[3];
    float* Out = (float*)d_out;

    cudaFuncSetAttribute(qkv_mma_kernel, cudaFuncAttributeMaxDynamicSharedMemorySize, SMEM_DYN);

    __half* xh_ptr = nullptr;
    cudaGetSymbolAddress((void**)&xh_ptr, g_Xh);

    const int n4 = (M_TOTAL * K_DIM) / 4;
    cvt_x_kernel<<<(n4 / 4 + 255) / 256, 256>>>((const float4*)X, (uint2*)xh_ptr, n4);
    cvt_w_kernel<<<(3 * R_DIM * K_DIM + 255) / 256, 256>>>(Wq, Wk, Wv);

    dim3 grid(3, M_TOTAL / BM);               // 3 x 197 = 591 CTAs = 1.997 waves @ 2/SM
    qkv_mma_kernel<<<grid, 128, SMEM_DYN>>>(Out);
}

// round 7
// speedup vs baseline: 1.2132x; 1.0628x over previous
#include <cuda_runtime.h>
#include <cuda_fp16.h>
#include <cstdint>

#define M_TOTAL 12608   // 64*197 (divisible by 64 -> no M guards)
#define K_DIM   768
#define R_DIM   192
#define BM      64
#define BN      192
#define BK      64      // fp16 elems per chunk = 128B row
#define NCHUNK  12
#define A_BYTES (BM * 128)            // 8192
#define B_BYTES (BN * 128)            // 24576
#define STAGE   (A_BYTES + B_BYTES)   // 32768
#define NSTAGE  2
#define SMEM_DYN (NSTAGE * STAGE + 1024)   // ~66KB -> 3 CTA/SM

#define SWZ(o) ((o) ^ (((o) >> 3) & 0x70))

// fp16 scratch (allocation-free __device__ globals)
__device__ __half g_Xh[(size_t)M_TOTAL * K_DIM];     // [M,K] row-major
__device__ __half g_Wh[(size_t)3 * R_DIM * K_DIM];   // [3][N=192][K=768] K-major

// ---------------- PTX helpers ----------------
__device__ __forceinline__ uint32_t smem_u32(const void* p) {
    uint32_t a;
    asm("{ .reg .u64 t; cvta.to.shared.u64 t, %1; cvt.u32.u64 %0, t; }" : "=r"(a) : "l"(p));
    return a;
}
__device__ __forceinline__ void cp16(uint32_t dst, const void* src) {
    asm volatile("cp.async.cg.shared.global [%0], [%1], 16;" :: "r"(dst), "l"(src) : "memory");
}
#define CP_COMMIT() asm volatile("cp.async.commit_group;" ::: "memory")
#define CP_WAIT0()  asm volatile("cp.async.wait_group 0;" ::: "memory")
#define CP_WAIT1()  asm volatile("cp.async.wait_group 1;" ::: "memory")

__device__ __forceinline__ void ldsm4(uint32_t* r, uint32_t addr) {
    asm volatile("ldmatrix.sync.aligned.m8n8.x4.shared.b16 {%0,%1,%2,%3}, [%4];"
                 : "=r"(r[0]), "=r"(r[1]), "=r"(r[2]), "=r"(r[3]) : "r"(addr));
}
__device__ __forceinline__ void mma16816(float* c, const uint32_t* a, const uint32_t* b) {
    asm volatile(
        "mma.sync.aligned.m16n8k16.row.col.f32.f16.f16.f32 "
        "{%0,%1,%2,%3}, {%4,%5,%6,%7}, {%8,%9}, {%0,%1,%2,%3};"
        : "+f"(c[0]), "+f"(c[1]), "+f"(c[2]), "+f"(c[3])
        : "r"(a[0]), "r"(a[1]), "r"(a[2]), "r"(a[3]), "r"(b[0]), "r"(b[1]));
}
__device__ __forceinline__ float gelu_exact(float x) {
    return 0.5f * x * (1.0f + erff(x * 0.70710678118654752f));
}

// ---------------- fused convert prepass (X + W in one launch) ----------------
#define XBLK 1182   // (12608*768/8 uint4) / (4*256)
#define WBLK 1728   // 442368 / 256
__global__ __launch_bounds__(256, 4)
void cvt_xw_kernel(const float4* __restrict__ X,
                   const float* __restrict__ Wq, const float* __restrict__ Wk,
                   const float* __restrict__ Wv, uint4* __restrict__ xh_out) {
    if (blockIdx.x < XBLK) {
        const int n_u4 = (M_TOTAL * K_DIM) / 8;              // 1210368
        const int t = blockIdx.x * blockDim.x + threadIdx.x;
        const int stride = XBLK * 256;
        float4 v[8];
        #pragma unroll
        for (int u = 0; u < 4; ++u) {
            int i = t + u * stride;
            if (i < n_u4) {
                v[2 * u + 0] = X[2 * i + 0];
                v[2 * u + 1] = X[2 * i + 1];
            }
        }
        #pragma unroll
        for (int u = 0; u < 4; ++u) {
            int i = t + u * stride;
            if (i < n_u4) {
                __half2 h0 = __floats2half2_rn(v[2*u].x,   v[2*u].y);
                __half2 h1 = __floats2half2_rn(v[2*u].z,   v[2*u].w);
                __half2 h2 = __floats2half2_rn(v[2*u+1].x, v[2*u+1].y);
                __half2 h3 = __floats2half2_rn(v[2*u+1].z, v[2*u+1].w);
                uint4 o;
                o.x = *reinterpret_cast<uint32_t*>(&h0);
                o.y = *reinterpret_cast<uint32_t*>(&h1);
                o.z = *reinterpret_cast<uint32_t*>(&h2);
                o.w = *reinterpret_cast<uint32_t*>(&h3);
                xh_out[i] = o;
            }
        }
    } else {
        int idx = (blockIdx.x - XBLK) * blockDim.x + threadIdx.x;
        const int per = R_DIM * K_DIM;
        if (idx < 3 * per) {
            int w = idx / per;
            int rem = idx - w * per;
            int n = rem / K_DIM;
            int k = rem - n * K_DIM;
            const float* W = (w == 0) ? Wq : (w == 1) ? Wk : Wv;
            g_Wh[idx] = __float2half_rn(W[k * R_DIM + n]);   // transpose -> K-major
        }
    }
}

// ---------------- chunk loader (cp.async, swizzled 128B rows) ----------------
__device__ __forceinline__ void load_chunk(int c, uint32_t st, const __half* Asrc,
                                           const __half* Bsrc, int tid) {
    // A: 64 rows x 8 16B-chunks = 512 -> 4 per thread (128 threads)
    #pragma unroll
    for (int u = 0; u < 4; ++u) {
        int idx = tid + u * 128;
        int row = idx >> 3;
        int j   = idx & 7;
        cp16(st + SWZ(row * 128 + j * 16),
             Asrc + (size_t)row * K_DIM + c * BK + j * 8);
    }
    // B: 192 rows x 8 = 1536 -> 12 per thread
    #pragma unroll
    for (int u = 0; u < 12; ++u) {
        int idx = tid + u * 128;
        int row = idx >> 3;
        int j   = idx & 7;
        cp16(st + A_BYTES + SWZ(row * 128 + j * 16),
             Bsrc + (size_t)row * K_DIM + c * BK + j * 8);
    }
}

// ---------------- GEMM: CTA 64x192, 4 warps (1x4), warp tile 64x48 ----------------
__global__ __launch_bounds__(128, 3)
void qkv_mma_kernel(float* __restrict__ Out) {
    extern __shared__ char dynsm[];
    const int tid  = threadIdx.x;
    const int wid  = tid >> 5;                // 0..3
    const int lane = tid & 31;
    const int nb   = blockIdx.x;              // 0..2 -> q/k/v
    const int bm   = blockIdx.y * BM;

    const int warp_n = wid * 48;

    uint32_t base = (smem_u32(dynsm) + 1023u) & ~1023u;

    const __half* Asrc = g_Xh + (size_t)bm * K_DIM;
    const __half* Bsrc = g_Wh + (size_t)nb * R_DIM * K_DIM;

    // per-lane ldmatrix offsets
    const int a_row_off = lane & 15;
    const int a_k_off   = (lane >> 4) * 16;
    const int b_n_off   = (lane & 7) | ((lane & 16) >> 1);
    const int b_k_off   = (lane & 8) ? 16 : 0;

    float acc[4][6][4];
    #pragma unroll
    for (int i = 0; i < 4; ++i)
        #pragma unroll
        for (int j = 0; j < 6; ++j)
            #pragma unroll
            for (int q = 0; q < 4; ++q) acc[i][j][q] = 0.0f;

    uint32_t afrag[2][4][4], bfrag[2][3][4];

    // prologue: chunks 0,1 in flight (2-stage ring)
    load_chunk(0, base, Asrc, Bsrc, tid);          CP_COMMIT();
    load_chunk(1, base + STAGE, Asrc, Bsrc, tid);  CP_COMMIT();

    for (int j = 0; j < NCHUNK; ++j) {
        if (j + 1 < NCHUNK) { CP_WAIT1(); } else { CP_WAIT0(); }
        __syncthreads();                 // chunk j resident in stage j%2

        const uint32_t a_sm = base + (j & 1) * STAGE;
        const uint32_t b_sm = a_sm + A_BYTES;

        // preload ks=0 fragments
        #pragma unroll
        for (int mf = 0; mf < 4; ++mf)
            ldsm4(afrag[0][mf], a_sm + SWZ((mf * 16 + a_row_off) * 128 + a_k_off));
        #pragma unroll
        for (int nf2 = 0; nf2 < 3; ++nf2)
            ldsm4(bfrag[0][nf2], b_sm + SWZ((warp_n + nf2 * 16 + b_n_off) * 128 + b_k_off));

        #pragma unroll
        for (int ks = 0; ks < 4; ++ks) {
            const int cur = ks & 1;
            if (ks < 3) {   // prefetch ks+1 frags while MMAs of ks run
                const int nxt = cur ^ 1;
                #pragma unroll
                for (int mf = 0; mf < 4; ++mf)
                    ldsm4(afrag[nxt][mf],
                          a_sm + SWZ((mf * 16 + a_row_off) * 128 + (ks + 1) * 32 + a_k_off));
                #pragma unroll
                for (int nf2 = 0; nf2 < 3; ++nf2)
                    ldsm4(bfrag[nxt][nf2],
                          b_sm + SWZ((warp_n + nf2 * 16 + b_n_off) * 128 + (ks + 1) * 32 + b_k_off));
            }
            #pragma unroll
            for (int mf = 0; mf < 4; ++mf)
                #pragma unroll
                for (int nf = 0; nf < 6; ++nf)
                    mma16816(acc[mf][nf], afrag[cur][mf], &bfrag[cur][nf >> 1][(nf & 1) * 2]);
        }

        __syncthreads();                 // all warps done reading stage j%2
        if (j + 2 < NCHUNK) {
            load_chunk(j + 2, base + (j & 1) * STAGE, Asrc, Bsrc, tid);
            CP_COMMIT();
        }
    }

    // ---- epilogue: GELU + float2 stores (no M guards: 12608 % 64 == 0)
    float* __restrict__ outbase =
        Out + (size_t)nb * (size_t)M_TOTAL * R_DIM + warp_n;
    const int rbase = bm + (lane >> 2);
    const int cbase = (lane & 3) * 2;
    #pragma unroll
    for (int mf = 0; mf < 4; ++mf) {
        #pragma unroll
        for (int half = 0; half < 2; ++half) {
            int row = rbase + mf * 16 + half * 8;
            float* op = outbase + (size_t)row * R_DIM + cbase;
            #pragma unroll
            for (int nf = 0; nf < 6; ++nf) {
                float2 o;
                o.x = gelu_exact(acc[mf][nf][half * 2 + 0]);
                o.y = gelu_exact(acc[mf][nf][half * 2 + 1]);
                *reinterpret_cast<float2*>(op + nf * 8) = o;
            }
        }
    }
}

extern "C" void kernel_launch(void* const* d_in, const int* in_sizes, int n_in,
                              void* d_out, int out_size) {
    const float* X  = (const float*)d_in[0];  // [64,197,768]
    const float* Wq = (const float*)d_in[1];  // [768,192]
    const float* Wk = (const float*)d_in[2];
    const float* Wv = (const float*)d_in[3];
    float* Out = (float*)d_out;

    cudaFuncSetAttribute(qkv_mma_kernel, cudaFuncAttributeMaxDynamicSharedMemorySize, SMEM_DYN);

    __half* xh_ptr = nullptr;
    cudaGetSymbolAddress((void**)&xh_ptr, g_Xh);

    cvt_xw_kernel<<<XBLK + WBLK, 256>>>((const float4*)X, Wq, Wk, Wv, (uint4*)xh_ptr);

    dim3 grid(3, M_TOTAL / BM);               // 3 x 197 = 591 CTAs
    qkv_mma_kernel<<<grid, 128, SMEM_DYN>>>(Out);
}